// round 16
// baseline (speedup 1.0000x reference)
#include <cuda_runtime.h>
#include <cstdint>
#include <cstddef>

#define BATCH    64
#define SEQ      2048
#define INPUT    8
#define HIDDEN   512
#define NUM_SEEDS 4
#define DD       12
#define OUTK     10
#define ALPHA_F  0.1f
#define K1_F     (0.1f * (500.0f/512.0f))
#define QSCALE   4194304.0f          /* 2^22 fixed-point scale for warp reduction */
#define QINV     (1.0f/4194304.0f)

typedef unsigned long long u64;

// native tanh (MUFU.TANH): 1 MUFU op, ~16cyc; rel err ~2^-11.
__device__ __forceinline__ float fast_tanh(float x) {
    float r;
    asm("tanh.approx.f32 %0, %1;" : "=f"(r) : "f"(x));
    return r;
}

// ---- packed f32x2 helpers (Blackwell FFMA2 via PTX) ----
__device__ __forceinline__ u64 pk2(float lo, float hi) {
    u64 r;
    asm("mov.b64 %0, {%1, %2};" : "=l"(r) : "f"(lo), "f"(hi));
    return r;
}
__device__ __forceinline__ float2 up2(u64 v) {
    float2 r;
    asm("mov.b64 {%0, %1}, %2;" : "=f"(r.x), "=f"(r.y) : "l"(v));
    return r;
}
__device__ __forceinline__ u64 fma2(u64 a, u64 b, u64 c) {
    u64 r;
    asm("fma.rn.f32x2 %0, %1, %2, %3;" : "=l"(r) : "l"(a), "l"(b), "l"(c));
    return r;
}

// ---------------- single fused kernel ----------------
// Prologue: mixture-combined clamped Cholesky Lc (12x12 smem, strided init),
// per-thread comb -> M/N/Iw regs. Main loop: R15's proven scan with the aix
// (input-projection) block SOFTWARE-PIPELINED one step ahead: a_{t+1} is
// computed in the post-barrier LDS/I2F latency shadow; the pre-barrier tail
// is just 2 fma2, so barrier arrival is no longer delayed by ~52 issue cyc.
__global__ __launch_bounds__(128, 1) void rnn_kernel(const float* __restrict__ x,
                                                     const float* __restrict__ means,
                                                     const float* __restrict__ L,
                                                     const float* __restrict__ mw,
                                                     const float* __restrict__ seeds,
                                                     const int* __restrict__ cur_seeds,
                                                     float* __restrict__ out) {
    const int b = blockIdx.x;
    const int tid = threadIdx.x;
    const int wid = tid >> 5, lane = tid & 31;
    const int s = cur_seeds[b];
    const int h0 = tid * 4;

    // ---- prologue: mixture-combined Lc, mc (identical math to old setup) ----
    __shared__ float Lc[DD][DD];
    __shared__ float mc[DD];
    {
        float w0 = fmaxf(mw[0], 1e-6f);
        float w1 = fmaxf(mw[1], 1e-6f);
        float inv = 1.0f / (w0 + w1);
        w0 *= inv; w1 *= inv;

        for (int i = tid; i < DD * DD; i += 128) {
            int d = i / DD, e = i - d * DD;
            float a = L[d * DD + e];
            float c = L[DD * DD + d * DD + e];
            float v = 0.0f;
            if (e < d) {
                v = w0 * a + w1 * c;
            } else if (e == d) {
                v = w0 * (fabsf(a - 1e-12f) + 1e-12f)
                  + w1 * (fabsf(c - 1e-12f) + 1e-12f);
            }
            Lc[d][e] = v;
        }
        if (tid < DD) mc[tid] = w0 * means[tid] + w1 * means[DD + tid];
    }
    __syncthreads();

    // per-thread comb for 4 hidden units -> m0,m1,n0,n1,I
    float m0v[4], m1v[4], n0v[4], n1v[4], Iv[4][INPUT];
    #pragma unroll
    for (int c = 0; c < 4; c++) {
        const float* srow = seeds + ((size_t)s * HIDDEN + (h0 + c)) * DD;
        float sd[DD];
        #pragma unroll
        for (int e = 0; e < DD; e++) sd[e] = srow[e];
        float comb[DD];
        #pragma unroll
        for (int d = 0; d < DD; d++) {
            float v = mc[d];
            for (int e = 0; e <= d; e++) v = fmaf(Lc[d][e], sd[e], v);
            comb[d] = v;
        }
        m0v[c] = comb[0]; m1v[c] = comb[1];
        n0v[c] = comb[2]; n1v[c] = comb[3];
        #pragma unroll
        for (int i = 0; i < INPUT; i++) Iv[c][i] = comb[4 + i];
    }

    // ---- pack loop constants (identical to R15) ----
    float4 N0 = make_float4(n0v[0] * QSCALE, n0v[1] * QSCALE,
                            n0v[2] * QSCALE, n0v[3] * QSCALE);
    float4 N1 = make_float4(n1v[0] * QSCALE, n1v[1] * QSCALE,
                            n1v[2] * QSCALE, n1v[3] * QSCALE);

    const float KQ = K1_F * QINV;
    const u64 M0A = pk2(m0v[0] * KQ, m0v[1] * KQ);
    const u64 M0B = pk2(m0v[2] * KQ, m0v[3] * KQ);
    const u64 M1A = pk2(m1v[0] * KQ, m1v[1] * KQ);
    const u64 M1B = pk2(m1v[2] * KQ, m1v[3] * KQ);

    u64 IwA[INPUT], IwB[INPUT];
    #pragma unroll
    for (int i = 0; i < INPUT; i++) {
        IwA[i] = pk2(ALPHA_F * Iv[0][i], ALPHA_F * Iv[1][i]);
        IwB[i] = pk2(ALPHA_F * Iv[2][i], ALPHA_F * Iv[3][i]);
    }

    const float* xb = x + (size_t)b * SEQ * INPUT;
    float* ob = out + (size_t)b * SEQ * OUTK;     // full output rows
    const float K1S = K1_F * QINV;
    const u64 C9 = pk2(0.9f, 0.9f);
    const u64 ZU = 0ull;

    __shared__ __align__(16) u64 isp[2][4];       // [parity][warp]: {iq0,iq1}

    u64 hA = ZU, hB = ZU;                         // packed (h0,h1),(h2,h3)
    float oa = 0.0f, obv = 0.0f;                  // rank scans (all threads)
    float accx = 0.0f;                            // x-only scan (lanes 2..9)
    const bool store_lane = (wid == 3) && (lane < OUTK);
    const bool is0 = (lane == 0), is1 = (lane == 1);
    const float* xgl = xb + ((lane - 2) & 7);     // this lane's x column

    float4 xA0 = *(const float4*)(xb + 0), xB0 = *(const float4*)(xb + 4);
    float4 xA1 = *(const float4*)(xb + 8), xB1 = *(const float4*)(xb + 12);

    // aix projection: outA/outB = (ALPHA*I) @ x_row (packed over unit pairs)
    #define AIX(XA, XB, outA, outB)                                               \
    {                                                                             \
        u64 xd0 = pk2(XA.x, XA.x), xd1 = pk2(XA.y, XA.y);                         \
        u64 xd2 = pk2(XA.z, XA.z), xd3 = pk2(XA.w, XA.w);                         \
        u64 xd4 = pk2(XB.x, XB.x), xd5 = pk2(XB.y, XB.y);                         \
        u64 xd6 = pk2(XB.z, XB.z), xd7 = pk2(XB.w, XB.w);                         \
        u64 tA = fma2(IwA[0], xd0, ZU);                                           \
        u64 tB = fma2(IwB[0], xd0, ZU);                                           \
        tA = fma2(IwA[1], xd1, tA);  tB = fma2(IwB[1], xd1, tB);                  \
        tA = fma2(IwA[2], xd2, tA);  tB = fma2(IwB[2], xd2, tB);                  \
        tA = fma2(IwA[3], xd3, tA);  tB = fma2(IwB[3], xd3, tB);                  \
        tA = fma2(IwA[4], xd4, tA);  tB = fma2(IwB[4], xd4, tB);                  \
        tA = fma2(IwA[5], xd5, tA);  tB = fma2(IwB[5], xd5, tB);                  \
        tA = fma2(IwA[6], xd6, tA);  tB = fma2(IwB[6], xd6, tB);                  \
        tA = fma2(IwA[7], xd7, tA);  tB = fma2(IwB[7], xd7, tB);                  \
        outA = tA; outB = tB;                                                     \
    }

    // a_0 precomputed before the loop
    u64 aCurA, aCurB;
    AIX(xA0, xB0, aCurA, aCurB);

    // XNA/XNB = x row for step T+1; its aix is computed post-barrier (shadow)
    #define RNN_STEP(PAR, T, XNA, XNB)                                            \
    {                                                                             \
        /* x column for the fused output scan (L1 broadcast hit, off-chain) */    \
        float xg = ALPHA_F * xgl[(size_t)(T) * INPUT];                            \
        float2 hx = up2(hA), hy = up2(hB);                                        \
        float th0 = fast_tanh(hx.x);                                              \
        float th1 = fast_tanh(hx.y);                                              \
        float th2 = fast_tanh(hy.x);                                              \
        float th3 = fast_tanh(hy.y);                                              \
        float q0 = fmaf(N0.x, th0, N0.y * th1) + fmaf(N0.z, th2, N0.w * th3);     \
        float q1 = fmaf(N1.x, th0, N1.y * th1) + fmaf(N1.z, th2, N1.w * th3);     \
        int iq0 = __float2int_rn(q0);                                             \
        int iq1 = __float2int_rn(q1);                                             \
        iq0 = __reduce_add_sync(0xffffffffu, iq0);                                \
        iq1 = __reduce_add_sync(0xffffffffu, iq1);                                \
        if (lane == 0)                                                            \
            isp[PAR][wid] = ((u64)(unsigned)iq0 << 32) | (unsigned)iq1;           \
        /* minimal pre-barrier tail: decay + precomputed input */                 \
        hA = fma2(C9, hA, aCurA);                                                 \
        hB = fma2(C9, hB, aCurB);                                                 \
        accx = fmaf(0.9f, accx, xg);                                              \
        __syncthreads();                                                          \
        /* LDS first (long latency)... */                                         \
        ulonglong2 w01 = *(const ulonglong2*)&isp[PAR][0];                        \
        ulonglong2 w23 = *(const ulonglong2*)&isp[PAR][2];                        \
        /* ...then fill the shadow with NEXT step's aix (independent) */          \
        AIX(XNA, XNB, aCurA, aCurB);                                              \
        int s0 = (int)(unsigned)(w01.x >> 32) + (int)(unsigned)(w01.y >> 32)      \
               + (int)(unsigned)(w23.x >> 32) + (int)(unsigned)(w23.y >> 32);     \
        int s1 = (int)(unsigned)w01.x + (int)(unsigned)w01.y                      \
               + (int)(unsigned)w23.x + (int)(unsigned)w23.y;                     \
        float p0 = (float)s0;                                                     \
        float p1 = (float)s1;                                                     \
        u64 p0d = pk2(p0, p0), p1d = pk2(p1, p1);                                 \
        hA = fma2(M0A, p0d, fma2(M1A, p1d, hA));                                  \
        hB = fma2(M0B, p0d, fma2(M1B, p1d, hB));                                  \
        oa  = fmaf(0.9f, oa,  K1S * p0);   /* all threads: symmetric streams */   \
        obv = fmaf(0.9f, obv, K1S * p1);                                          \
        float oval = is0 ? oa : (is1 ? obv : accx);                               \
        if (store_lane) ob[(size_t)(T) * OUTK + lane] = oval;                     \
    }

    for (int t = 0; t < SEQ; t += 2) {
        int tf = (t + 2 <= SEQ - 2) ? t + 2 : SEQ - 2;
        float4 nA0 = *(const float4*)(xb + (size_t)tf * INPUT);
        float4 nB0 = *(const float4*)(xb + (size_t)tf * INPUT + 4);
        float4 nA1 = *(const float4*)(xb + (size_t)(tf + 1) * INPUT);
        float4 nB1 = *(const float4*)(xb + (size_t)(tf + 1) * INPUT + 4);

        RNN_STEP(0, t,     xA1, xB1);   // computes a_{t+1} in shadow
        RNN_STEP(1, t + 1, nA0, nB0);   // computes a_{t+2} in shadow

        xA0 = nA0; xB0 = nB0; xA1 = nA1; xB1 = nB1;
    }
    #undef RNN_STEP
    #undef AIX
}

// ---------------- launch: ONE kernel ----------------
extern "C" void kernel_launch(void* const* d_in, const int* in_sizes, int n_in,
                              void* d_out, int out_size) {
    const float* x     = (const float*)d_in[0];   // (64,2048,8)
    const float* means = (const float*)d_in[1];   // (2,12)
    const float* L     = (const float*)d_in[2];   // (2,12,12)
    const float* mw    = (const float*)d_in[3];   // (2,)
    const float* seeds = (const float*)d_in[4];   // (4,512,12)
    const int*   cs    = (const int*)d_in[5];     // (64,)
    float* out = (float*)d_out;                   // (64,2048,10)

    rnn_kernel<<<BATCH, 128>>>(x, means, L, mw, seeds, cs, out);
}